// round 5
// baseline (speedup 1.0000x reference)
#include <cuda_runtime.h>

// Problem constants (z: [8192, 20, 256] f32, labels: [8192] i32, K=10)
#define NUM_LABELS 10
#define B_ROWS     8192
#define CH         5120          // C*H = 20*256
#define EPS        1e-8f

#define TPB            128       // threads per CTA in accumulate kernel
#define COLS_PER_CTA   512       // TPB * 4 (float4 per thread)
#define ROWS_PER_CHUNK 128
#define COL_BLOCKS     (CH / COLS_PER_CTA)          // 10
#define ROW_CHUNKS     (B_ROWS / ROWS_PER_CHUNK)    // 64

// Kernel-1 geometry: CTAs 0..ZERO_CTAS-1 zero accumulators, CTA ZERO_CTAS hists
#define K1_TPB     512
#define ZERO_CTAS  40            // 40*512 = 20480 threads >= 12800 float4 per array

// Scratch (allocation-free: __device__ globals)
__device__ __align__(16) float g_sum [NUM_LABELS * CH];
__device__ __align__(16) float g_sum2[NUM_LABELS * CH];
__device__ int g_counts[NUM_LABELS];

// ---------------------------------------------------------------------------
// Kernel 1: zero accumulators + out[0] (CTAs 0..39); label histogram (CTA 40).
// Histogram uses per-warp smem bins (no match/shfl chains -> short critical path).
// ---------------------------------------------------------------------------
__global__ __launch_bounds__(K1_TPB) void prep_kernel(const int* __restrict__ labels,
                                                      float* __restrict__ out) {
    if (blockIdx.x < ZERO_CTAS) {
        int i = blockIdx.x * K1_TPB + threadIdx.x;          // float4 index
        const int n4 = (NUM_LABELS * CH) / 4;               // 12800
        float4 zv = make_float4(0.f, 0.f, 0.f, 0.f);
        if (i < n4) {
            ((float4*)g_sum)[i]  = zv;
            ((float4*)g_sum2)[i] = zv;
        }
        if (i == 0) out[0] = 0.0f;
        return;
    }

    // ---- histogram path: single CTA, 512 threads = 16 warps ----
    __shared__ int bins[16][NUM_LABELS];
    const int tid = threadIdx.x;
    const int wid = tid >> 5;

    if (tid < 16 * NUM_LABELS) ((int*)bins)[tid] = 0;
    __syncthreads();

    const int4* __restrict__ lab4 = (const int4*)labels;
    // 2048 int4 / 512 threads -> 4 iterations, atomics into this warp's row
    #pragma unroll
    for (int it = 0; it < (B_ROWS / 4) / K1_TPB; it++) {
        int4 v = lab4[it * K1_TPB + tid];
        atomicAdd(&bins[wid][v.x], 1);
        atomicAdd(&bins[wid][v.y], 1);
        atomicAdd(&bins[wid][v.z], 1);
        atomicAdd(&bins[wid][v.w], 1);
    }
    __syncthreads();

    if (tid < NUM_LABELS) {
        int acc = 0;
        #pragma unroll
        for (int w = 0; w < 16; w++) acc += bins[w][tid];
        g_counts[tid] = acc;
    }
}

// ---------------------------------------------------------------------------
// Kernel 2: one-pass segmented sum / sum-of-squares with LOCAL label sort.
// grid = (COL_BLOCKS, ROW_CHUNKS), 128 threads, float4/thread, MLP=8.
// Each CTA counting-sorts its own 128 labels in smem, then walks rows in
// label-grouped order so register accumulators flush ~10 times total.
// ---------------------------------------------------------------------------
__device__ __forceinline__ void flush_acc(int lab, int colBase,
                                          float4& a, float4& a2) {
    int base = lab * CH + colBase;
    atomicAdd(&g_sum [base + 0], a.x);
    atomicAdd(&g_sum [base + 1], a.y);
    atomicAdd(&g_sum [base + 2], a.z);
    atomicAdd(&g_sum [base + 3], a.w);
    atomicAdd(&g_sum2[base + 0], a2.x);
    atomicAdd(&g_sum2[base + 1], a2.y);
    atomicAdd(&g_sum2[base + 2], a2.z);
    atomicAdd(&g_sum2[base + 3], a2.w);
    a  = make_float4(0.f, 0.f, 0.f, 0.f);
    a2 = make_float4(0.f, 0.f, 0.f, 0.f);
}

__global__ __launch_bounds__(TPB) void accum_kernel(const float* __restrict__ z,
                                                    const int* __restrict__ labels) {
    __shared__ int s_rl[ROWS_PER_CHUNK];
    __shared__ int sh_cnt[NUM_LABELS];
    __shared__ int sh_base[NUM_LABELS];

    const int tid  = threadIdx.x;
    const int lane = tid & 31;
    const int cb   = blockIdx.x;   // column block 0..9
    const int rc   = blockIdx.y;   // row chunk   0..63

    // ---- local counting sort of this chunk's 128 labels ----
    const int row = rc * ROWS_PER_CHUNK + tid;
    const int lab_mine = labels[row];
    if (tid < NUM_LABELS) sh_cnt[tid] = 0;
    __syncthreads();

    unsigned mask = __match_any_sync(0xffffffffu, lab_mine);
    int leader = __ffs(mask) - 1;
    int rank   = __popc(mask & ((1u << lane) - 1u));
    int wbase = 0;
    if (lane == leader) wbase = atomicAdd(&sh_cnt[lab_mine], __popc(mask));
    wbase = __shfl_sync(0xffffffffu, wbase, leader);
    __syncthreads();

    if (tid == 0) {
        int acc = 0;
        #pragma unroll
        for (int k = 0; k < NUM_LABELS; k++) { sh_base[k] = acc; acc += sh_cnt[k]; }
    }
    __syncthreads();
    s_rl[sh_base[lab_mine] + wbase + rank] = (row << 4) | lab_mine;
    __syncthreads();

    // ---- bandwidth mainloop (unchanged from R2) ----
    const float4* __restrict__ z4 = (const float4*)z;
    const int col4    = cb * (COLS_PER_CTA / 4) + tid;   // float4 index in row
    const int colBase = cb * COLS_PER_CTA + tid * 4;     // scalar column base

    float4 a  = make_float4(0.f, 0.f, 0.f, 0.f);
    float4 a2 = make_float4(0.f, 0.f, 0.f, 0.f);
    int cur = s_rl[0] & 15;

    for (int i = 0; i < ROWS_PER_CHUNK; i += 8) {
        int    rl[8];
        float4 v[8];
        #pragma unroll
        for (int u = 0; u < 8; u++) rl[u] = s_rl[i + u];
        #pragma unroll
        for (int u = 0; u < 8; u++) v[u] = z4[(rl[u] >> 4) * (CH / 4) + col4];

        #pragma unroll
        for (int u = 0; u < 8; u++) {
            int lab = rl[u] & 15;
            if (lab != cur) { flush_acc(cur, colBase, a, a2); cur = lab; }
            a.x += v[u].x; a.y += v[u].y; a.z += v[u].z; a.w += v[u].w;
            a2.x = fmaf(v[u].x, v[u].x, a2.x);
            a2.y = fmaf(v[u].y, v[u].y, a2.y);
            a2.z = fmaf(v[u].z, v[u].z, a2.z);
            a2.w = fmaf(v[u].w, v[u].w, a2.w);
        }
    }
    flush_acc(cur, colBase, a, a2);
}

// ---------------------------------------------------------------------------
// Kernel 3: finalize.  grid = (NUM_LABELS, CH/1024), 1024 thr, 1 cell/thread.
// sse(k,j) = q - 2*m'*s + n*m'^2, m' = s/n - EPS; CTA-reduce; atomicAdd.
// (out[0] is zeroed by prep_kernel.)
// ---------------------------------------------------------------------------
__global__ __launch_bounds__(1024) void finalize_kernel(float* __restrict__ out) {
    __shared__ float sh[32];
    const int k   = blockIdx.x;
    const int j   = blockIdx.y * 1024 + threadIdx.x;
    const int tid = threadIdx.x;

    float n = (float)g_counts[k];
    float acc = 0.0f;
    if (n > 0.0f) {
        int idx  = k * CH + j;
        float s  = g_sum[idx];
        float q  = g_sum2[idx];
        float mp = s / n - EPS;
        float e  = q - 2.0f * mp * s + n * mp * mp;
        acc = e / (n * (float)CH);
    }
    #pragma unroll
    for (int o = 16; o > 0; o >>= 1) acc += __shfl_down_sync(0xffffffffu, acc, o);
    if ((tid & 31) == 0) sh[tid >> 5] = acc;
    __syncthreads();
    if (tid < 32) {
        float v = sh[tid];
        #pragma unroll
        for (int o = 16; o > 0; o >>= 1) v += __shfl_down_sync(0xffffffffu, v, o);
        if (tid == 0) atomicAdd(out, v);
    }
}

// ---------------------------------------------------------------------------
extern "C" void kernel_launch(void* const* d_in, const int* in_sizes, int n_in,
                              void* d_out, int out_size) {
    const float* z      = (const float*)d_in[0];
    const int*   labels = (const int*)d_in[1];
    (void)in_sizes; (void)n_in; (void)out_size;

    prep_kernel<<<ZERO_CTAS + 1, K1_TPB>>>(labels, (float*)d_out);
    accum_kernel<<<dim3(COL_BLOCKS, ROW_CHUNKS), TPB>>>(z, labels);
    finalize_kernel<<<dim3(NUM_LABELS, CH / 1024), 1024>>>((float*)d_out);
}

// round 6
// speedup vs baseline: 1.3279x; 1.3279x over previous
#include <cuda_runtime.h>

// Problem constants (z: [8192, 20, 256] f32, labels: [8192] i32, K=10)
#define NUM_LABELS 10
#define B_ROWS     8192
#define CH         5120          // C*H = 20*256
#define EPS        1e-8f

#define TPB            128       // threads per CTA in accumulate kernel
#define COLS_PER_CTA   512       // TPB * 4 (float4 per thread)
#define ROWS_PER_CHUNK 128
#define COL_BLOCKS     (CH / COLS_PER_CTA)          // 10
#define ROW_CHUNKS     (B_ROWS / ROWS_PER_CHUNK)    // 64

// Kernel-1 geometry: 40 zero CTAs + 1 histogram CTA + 4 scatter CTAs
#define K1_TPB       512
#define ZERO_CTAS    40          // 40*512 = 20480 threads >= 12800 float4 per array
#define HIST_CTA     ZERO_CTAS   // CTA 40
#define SCATTER_CTAS 4           // CTAs 41..44, 2048 labels each

// Scratch (allocation-free: __device__ globals)
__device__ __align__(16) float g_sum [NUM_LABELS * CH];
__device__ __align__(16) float g_sum2[NUM_LABELS * CH];
__device__ int g_rl[B_ROWS];        // (row << 4) | label, grouped by label
__device__ int g_counts[NUM_LABELS];
__device__ int g_off[NUM_LABELS];   // atomic scatter cursors (set fresh per replay)
__device__ volatile int g_flag;     // 0 at start of every replay (reset by finalize)

// ---------------------------------------------------------------------------
// Kernel 1: zero (CTAs 0..39) | histogram+bases (CTA 40) | scatter (41..44).
// Scatter CTAs spin on g_flag raised by the histogram CTA; all 45 CTAs are
// co-resident in one wave (45 < 148 SMs) so the spin cannot deadlock.
// ---------------------------------------------------------------------------
__global__ __launch_bounds__(K1_TPB) void prep_kernel(const int* __restrict__ labels,
                                                      float* __restrict__ out) {
    const int tid = threadIdx.x;

    if (blockIdx.x < ZERO_CTAS) {
        int i = blockIdx.x * K1_TPB + tid;                  // float4 index
        const int n4 = (NUM_LABELS * CH) / 4;               // 12800
        float4 zv = make_float4(0.f, 0.f, 0.f, 0.f);
        if (i < n4) {
            ((float4*)g_sum)[i]  = zv;
            ((float4*)g_sum2)[i] = zv;
        }
        if (i == 0) out[0] = 0.0f;
        return;
    }

    if (blockIdx.x == HIST_CTA) {
        // ---- histogram: 512 threads = 16 warps, per-warp smem bins ----
        __shared__ int bins[16][NUM_LABELS];
        __shared__ int sh_cnt[NUM_LABELS];
        const int wid = tid >> 5;

        if (tid < 16 * NUM_LABELS) ((int*)bins)[tid] = 0;
        __syncthreads();

        const int4* __restrict__ lab4 = (const int4*)labels;
        #pragma unroll
        for (int it = 0; it < (B_ROWS / 4) / K1_TPB; it++) {
            int4 v = lab4[it * K1_TPB + tid];
            atomicAdd(&bins[wid][v.x], 1);
            atomicAdd(&bins[wid][v.y], 1);
            atomicAdd(&bins[wid][v.z], 1);
            atomicAdd(&bins[wid][v.w], 1);
        }
        __syncthreads();

        if (tid < NUM_LABELS) {
            int acc = 0;
            #pragma unroll
            for (int w = 0; w < 16; w++) acc += bins[w][tid];
            sh_cnt[tid] = acc;
            g_counts[tid] = acc;
        }
        __syncthreads();
        if (tid == 0) {
            int acc = 0;
            #pragma unroll
            for (int k = 0; k < NUM_LABELS; k++) { g_off[k] = acc; acc += sh_cnt[k]; }
            __threadfence();
            g_flag = 1;                   // release: bases are visible
        }
        return;
    }

    // ---- scatter CTAs (41..44): 2048 labels each, warp-aggregated atomics ----
    {
        if (tid == 0) { while (g_flag == 0) { } }
        __syncthreads();
        __threadfence();                  // acquire: see g_off bases

        const int lane = tid & 31;
        const int cta  = blockIdx.x - (HIST_CTA + 1);       // 0..3
        const int4* __restrict__ lab4 = (const int4*)labels;
        int i4 = cta * K1_TPB + tid;                        // int4 index, one per thread
        int4 v = lab4[i4];
        int b0 = i4 * 4;
        #pragma unroll
        for (int j = 0; j < 4; j++) {
            int lab = (j == 0) ? v.x : (j == 1) ? v.y : (j == 2) ? v.z : v.w;
            unsigned mask = __match_any_sync(0xffffffffu, lab);
            int leader = __ffs(mask) - 1;
            int rank   = __popc(mask & ((1u << lane) - 1u));
            int base = 0;
            if (lane == leader) base = atomicAdd(&g_off[lab], __popc(mask));
            base = __shfl_sync(0xffffffffu, base, leader);
            g_rl[base + rank] = ((b0 + j) << 4) | lab;
        }
    }
}

// ---------------------------------------------------------------------------
// Kernel 2: one-pass segmented sum / sum-of-squares (pristine R2/R4 body).
// grid = (COL_BLOCKS, ROW_CHUNKS), 128 threads, float4/thread, MLP=8.
// Rows walked in globally label-grouped order -> ~2 flushes per CTA.
// ---------------------------------------------------------------------------
__device__ __forceinline__ void flush_acc(int lab, int colBase,
                                          float4& a, float4& a2) {
    int base = lab * CH + colBase;
    atomicAdd(&g_sum [base + 0], a.x);
    atomicAdd(&g_sum [base + 1], a.y);
    atomicAdd(&g_sum [base + 2], a.z);
    atomicAdd(&g_sum [base + 3], a.w);
    atomicAdd(&g_sum2[base + 0], a2.x);
    atomicAdd(&g_sum2[base + 1], a2.y);
    atomicAdd(&g_sum2[base + 2], a2.z);
    atomicAdd(&g_sum2[base + 3], a2.w);
    a  = make_float4(0.f, 0.f, 0.f, 0.f);
    a2 = make_float4(0.f, 0.f, 0.f, 0.f);
}

__global__ __launch_bounds__(TPB) void accum_kernel(const float* __restrict__ z) {
    __shared__ int s_rl[ROWS_PER_CHUNK];
    const int tid = threadIdx.x;
    const int cb  = blockIdx.x;   // column block 0..9
    const int rc  = blockIdx.y;   // row chunk   0..63

    s_rl[tid] = g_rl[rc * ROWS_PER_CHUNK + tid];
    __syncthreads();

    const float4* __restrict__ z4 = (const float4*)z;
    const int col4    = cb * (COLS_PER_CTA / 4) + tid;   // float4 index in row
    const int colBase = cb * COLS_PER_CTA + tid * 4;     // scalar column base

    float4 a  = make_float4(0.f, 0.f, 0.f, 0.f);
    float4 a2 = make_float4(0.f, 0.f, 0.f, 0.f);
    int cur = s_rl[0] & 15;

    for (int i = 0; i < ROWS_PER_CHUNK; i += 8) {
        int    rl[8];
        float4 v[8];
        #pragma unroll
        for (int u = 0; u < 8; u++) rl[u] = s_rl[i + u];
        #pragma unroll
        for (int u = 0; u < 8; u++) v[u] = z4[(rl[u] >> 4) * (CH / 4) + col4];

        #pragma unroll
        for (int u = 0; u < 8; u++) {
            int lab = rl[u] & 15;
            if (lab != cur) { flush_acc(cur, colBase, a, a2); cur = lab; }
            a.x += v[u].x; a.y += v[u].y; a.z += v[u].z; a.w += v[u].w;
            a2.x = fmaf(v[u].x, v[u].x, a2.x);
            a2.y = fmaf(v[u].y, v[u].y, a2.y);
            a2.z = fmaf(v[u].z, v[u].z, a2.z);
            a2.w = fmaf(v[u].w, v[u].w, a2.w);
        }
    }
    flush_acc(cur, colBase, a, a2);
}

// ---------------------------------------------------------------------------
// Kernel 3: finalize.  grid = (NUM_LABELS, CH/1024), 1024 thr, 1 cell/thread.
// sse(k,j) = q - 2*m'*s + n*m'^2, m' = s/n - EPS; CTA-reduce; atomicAdd.
// Also resets g_flag for the next graph replay.
// ---------------------------------------------------------------------------
__global__ __launch_bounds__(1024) void finalize_kernel(float* __restrict__ out) {
    __shared__ float sh[32];
    const int k   = blockIdx.x;
    const int j   = blockIdx.y * 1024 + threadIdx.x;
    const int tid = threadIdx.x;

    if (k == 0 && blockIdx.y == 0 && tid == 0) g_flag = 0;   // reset for next replay

    float n = (float)g_counts[k];
    float acc = 0.0f;
    if (n > 0.0f) {
        int idx  = k * CH + j;
        float s  = g_sum[idx];
        float q  = g_sum2[idx];
        float mp = s / n - EPS;
        float e  = q - 2.0f * mp * s + n * mp * mp;
        acc = e / (n * (float)CH);
    }
    #pragma unroll
    for (int o = 16; o > 0; o >>= 1) acc += __shfl_down_sync(0xffffffffu, acc, o);
    if ((tid & 31) == 0) sh[tid >> 5] = acc;
    __syncthreads();
    if (tid < 32) {
        float v = sh[tid];
        #pragma unroll
        for (int o = 16; o > 0; o >>= 1) v += __shfl_down_sync(0xffffffffu, v, o);
        if (tid == 0) atomicAdd(out, v);
    }
}

// ---------------------------------------------------------------------------
extern "C" void kernel_launch(void* const* d_in, const int* in_sizes, int n_in,
                              void* d_out, int out_size) {
    const float* z      = (const float*)d_in[0];
    const int*   labels = (const int*)d_in[1];
    (void)in_sizes; (void)n_in; (void)out_size;

    prep_kernel<<<ZERO_CTAS + 1 + SCATTER_CTAS, K1_TPB>>>(labels, (float*)d_out);
    accum_kernel<<<dim3(COL_BLOCKS, ROW_CHUNKS), TPB>>>(z);
    finalize_kernel<<<dim3(NUM_LABELS, CH / 1024), 1024>>>((float*)d_out);
}

// round 8
// speedup vs baseline: 1.3325x; 1.0034x over previous
#include <cuda_runtime.h>

// Problem constants (z: [8192, 20, 256] f32, labels: [8192] i32, K=10)
#define NUM_LABELS 10
#define B_ROWS     8192
#define CH         5120          // C*H = 20*256
#define EPS        1e-8f

#define TPB            128       // threads per CTA in accumulate kernel
#define COLS_PER_CTA   512       // TPB * 4 (float4 per thread)
#define ROWS_PER_CHUNK 128
#define COL_BLOCKS     (CH / COLS_PER_CTA)          // 10
#define ROW_CHUNKS     (B_ROWS / ROWS_PER_CHUNK)    // 64

// Kernel-1 geometry: 40 zero CTAs + 4 independent scatter CTAs
#define K1_TPB       512
#define ZERO_CTAS    40          // 40*512 = 20480 threads >= 12800 float4 per array
#define SCATTER_CTAS 4           // CTAs 40..43, each scatters one quarter
#define QUARTER      (B_ROWS / SCATTER_CTAS)        // 2048 labels
#define QUARTER4     (QUARTER / 4)                  // 512 int4

// Scratch (allocation-free: __device__ globals)
__device__ __align__(16) float g_sum [NUM_LABELS * CH];
__device__ __align__(16) float g_sum2[NUM_LABELS * CH];
__device__ int g_rl[B_ROWS];        // (row << 4) | label, grouped by label
__device__ int g_counts[NUM_LABELS];

// ---------------------------------------------------------------------------
// Kernel 1: zero (CTAs 0..39) | independent scatter CTAs (40..43).
// Each scatter CTA redundantly histograms ALL quarters (32 KB of labels,
// L2-resident), derives its own global bases, and scatters its quarter.
// No inter-CTA communication at all.
// ---------------------------------------------------------------------------
__global__ __launch_bounds__(K1_TPB) void prep_kernel(const int* __restrict__ labels,
                                                      float* __restrict__ out) {
    const int tid = threadIdx.x;

    if (blockIdx.x < ZERO_CTAS) {
        int i = blockIdx.x * K1_TPB + tid;                  // float4 index
        const int n4 = (NUM_LABELS * CH) / 4;               // 12800
        float4 zv = make_float4(0.f, 0.f, 0.f, 0.f);
        if (i < n4) {
            ((float4*)g_sum)[i]  = zv;
            ((float4*)g_sum2)[i] = zv;
        }
        if (i == 0) out[0] = 0.0f;
        return;
    }

    // ---- scatter CTA c (c = 0..3): full histogram + scatter quarter c ----
    __shared__ int bins[16][NUM_LABELS];     // per-warp bins; warp w counts quarter w/4
    __shared__ int hist_q[SCATTER_CTAS][NUM_LABELS];
    __shared__ int cursor[NUM_LABELS];       // scatter cursors for my quarter

    const int c    = blockIdx.x - ZERO_CTAS;
    const int wid  = tid >> 5;
    const int lane = tid & 31;
    const int4* __restrict__ lab4 = (const int4*)labels;

    if (tid < 16 * NUM_LABELS) ((int*)bins)[tid] = 0;
    __syncthreads();

    // Warps [4q, 4q+4) histogram quarter q: 512 int4 over 128 threads -> 4 each
    {
        const int q   = wid >> 2;                       // quarter this warp counts
        const int t128 = (wid & 3) * 32 + lane;         // 0..127 within quarter team
        #pragma unroll
        for (int it = 0; it < QUARTER4 / 128; it++) {   // 4 iterations
            int4 v = lab4[q * QUARTER4 + it * 128 + t128];
            atomicAdd(&bins[wid][v.x], 1);
            atomicAdd(&bins[wid][v.y], 1);
            atomicAdd(&bins[wid][v.z], 1);
            atomicAdd(&bins[wid][v.w], 1);
        }
    }
    __syncthreads();

    // Reduce per-warp bins into per-quarter histograms
    if (tid < SCATTER_CTAS * NUM_LABELS) {
        int q = tid / NUM_LABELS, k = tid % NUM_LABELS;
        hist_q[q][k] = bins[4*q+0][k] + bins[4*q+1][k] + bins[4*q+2][k] + bins[4*q+3][k];
    }
    __syncthreads();

    // Global prefix + my quarter's starting base per label
    if (tid == 0) {
        int total[NUM_LABELS];
        #pragma unroll
        for (int k = 0; k < NUM_LABELS; k++)
            total[k] = hist_q[0][k] + hist_q[1][k] + hist_q[2][k] + hist_q[3][k];
        int acc = 0;
        #pragma unroll
        for (int k = 0; k < NUM_LABELS; k++) {
            int base = acc;                              // global start of label k
            for (int q = 0; q < c; q++) base += hist_q[q][k];
            cursor[k] = base;
            acc += total[k];
        }
        if (c == 0) {
            #pragma unroll
            for (int k = 0; k < NUM_LABELS; k++) g_counts[k] = total[k];
        }
    }
    __syncthreads();

    // Scatter my quarter: 512 threads x 1 int4, warp-aggregated smem atomics
    {
        int i4 = c * QUARTER4 + tid;
        int4 v = lab4[i4];
        int b0 = i4 * 4;
        #pragma unroll
        for (int j = 0; j < 4; j++) {
            int lab = (j == 0) ? v.x : (j == 1) ? v.y : (j == 2) ? v.z : v.w;
            unsigned mask = __match_any_sync(0xffffffffu, lab);
            int leader = __ffs(mask) - 1;
            int rank   = __popc(mask & ((1u << lane) - 1u));
            int base = 0;
            if (lane == leader) base = atomicAdd(&cursor[lab], __popc(mask));
            base = __shfl_sync(0xffffffffu, base, leader);
            g_rl[base + rank] = ((b0 + j) << 4) | lab;
        }
    }
}

// ---------------------------------------------------------------------------
// Kernel 2: one-pass segmented sum / sum-of-squares (pristine R2/R4 body).
// grid = (COL_BLOCKS, ROW_CHUNKS), 128 threads, float4/thread, MLP=8.
// Rows walked in globally label-grouped order -> ~2 flushes per CTA.
// ---------------------------------------------------------------------------
__device__ __forceinline__ void flush_acc(int lab, int colBase,
                                          float4& a, float4& a2) {
    int base = lab * CH + colBase;
    atomicAdd(&g_sum [base + 0], a.x);
    atomicAdd(&g_sum [base + 1], a.y);
    atomicAdd(&g_sum [base + 2], a.z);
    atomicAdd(&g_sum [base + 3], a.w);
    atomicAdd(&g_sum2[base + 0], a2.x);
    atomicAdd(&g_sum2[base + 1], a2.y);
    atomicAdd(&g_sum2[base + 2], a2.z);
    atomicAdd(&g_sum2[base + 3], a2.w);
    a  = make_float4(0.f, 0.f, 0.f, 0.f);
    a2 = make_float4(0.f, 0.f, 0.f, 0.f);
}

__global__ __launch_bounds__(TPB) void accum_kernel(const float* __restrict__ z) {
    __shared__ int s_rl[ROWS_PER_CHUNK];
    const int tid = threadIdx.x;
    const int cb  = blockIdx.x;   // column block 0..9
    const int rc  = blockIdx.y;   // row chunk   0..63

    s_rl[tid] = g_rl[rc * ROWS_PER_CHUNK + tid];
    __syncthreads();

    const float4* __restrict__ z4 = (const float4*)z;
    const int col4    = cb * (COLS_PER_CTA / 4) + tid;   // float4 index in row
    const int colBase = cb * COLS_PER_CTA + tid * 4;     // scalar column base

    float4 a  = make_float4(0.f, 0.f, 0.f, 0.f);
    float4 a2 = make_float4(0.f, 0.f, 0.f, 0.f);
    int cur = s_rl[0] & 15;

    for (int i = 0; i < ROWS_PER_CHUNK; i += 8) {
        int    rl[8];
        float4 v[8];
        #pragma unroll
        for (int u = 0; u < 8; u++) rl[u] = s_rl[i + u];
        #pragma unroll
        for (int u = 0; u < 8; u++) v[u] = z4[(rl[u] >> 4) * (CH / 4) + col4];

        #pragma unroll
        for (int u = 0; u < 8; u++) {
            int lab = rl[u] & 15;
            if (lab != cur) { flush_acc(cur, colBase, a, a2); cur = lab; }
            a.x += v[u].x; a.y += v[u].y; a.z += v[u].z; a.w += v[u].w;
            a2.x = fmaf(v[u].x, v[u].x, a2.x);
            a2.y = fmaf(v[u].y, v[u].y, a2.y);
            a2.z = fmaf(v[u].z, v[u].z, a2.z);
            a2.w = fmaf(v[u].w, v[u].w, a2.w);
        }
    }
    flush_acc(cur, colBase, a, a2);
}

// ---------------------------------------------------------------------------
// Kernel 3: finalize.  grid = (NUM_LABELS, CH/1024), 1024 thr, 1 cell/thread.
// sse(k,j) = q - 2*m'*s + n*m'^2, m' = s/n - EPS; CTA-reduce; atomicAdd.
// (out[0] is zeroed by prep_kernel.)
// ---------------------------------------------------------------------------
__global__ __launch_bounds__(1024) void finalize_kernel(float* __restrict__ out) {
    __shared__ float sh[32];
    const int k   = blockIdx.x;
    const int j   = blockIdx.y * 1024 + threadIdx.x;
    const int tid = threadIdx.x;

    float n = (float)g_counts[k];
    float acc = 0.0f;
    if (n > 0.0f) {
        int idx  = k * CH + j;
        float s  = g_sum[idx];
        float q  = g_sum2[idx];
        float mp = s / n - EPS;
        float e  = q - 2.0f * mp * s + n * mp * mp;
        acc = e / (n * (float)CH);
    }
    #pragma unroll
    for (int o = 16; o > 0; o >>= 1) acc += __shfl_down_sync(0xffffffffu, acc, o);
    if ((tid & 31) == 0) sh[tid >> 5] = acc;
    __syncthreads();
    if (tid < 32) {
        float v = sh[tid];
        #pragma unroll
        for (int o = 16; o > 0; o >>= 1) v += __shfl_down_sync(0xffffffffu, v, o);
        if (tid == 0) atomicAdd(out, v);
    }
}

// ---------------------------------------------------------------------------
extern "C" void kernel_launch(void* const* d_in, const int* in_sizes, int n_in,
                              void* d_out, int out_size) {
    const float* z      = (const float*)d_in[0];
    const int*   labels = (const int*)d_in[1];
    (void)in_sizes; (void)n_in; (void)out_size;

    prep_kernel<<<ZERO_CTAS + SCATTER_CTAS, K1_TPB>>>(labels, (float*)d_out);
    accum_kernel<<<dim3(COL_BLOCKS, ROW_CHUNKS), TPB>>>(z);
    finalize_kernel<<<dim3(NUM_LABELS, CH / 1024), 1024>>>((float*)d_out);
}